// round 7
// baseline (speedup 1.0000x reference)
#include <cuda_runtime.h>
#include <cstdint>

// WindowWarp R7: R6 gather path (warp = 8 float4-lanes x 4 t-rows, 8
// front-batched LDG.128, 256thr/8CTA launch bounds) + TMA bulk store:
// block accumulates its 32 contiguous output rows (8KB) in smem, then one
// cp.async.bulk.global.shared::cta per block. Stores leave via the TMA
// engine as 8KB sequential bursts, freeing L1tex/LSU for the gathers.
// B=256, T=2048, C=64, WARP_SIZE=205, L_MAX=2253.

#define BB 256
#define TT 2048
#define CC 64
#define ROWF4 (CC / 4)   // 16 float4 per row
#define TROWS 32         // t rows per block
#define TILE_BYTES (TROWS * CC * 4)   // 8192

__device__ __forceinline__ uint32_t smem_u32(const void* p) {
    uint32_t a;
    asm("{ .reg .u64 t; cvta.to.shared.u64 t, %1; cvt.u32.u64 %0, t; }"
        : "=r"(a) : "l"(p));
    return a;
}

__global__ void __launch_bounds__(256, 8) window_warp_kernel(
    const float* __restrict__ x,
    const float* __restrict__ warp_scales,
    const int*   __restrict__ window_starts,
    float* __restrict__ out)
{
    __shared__ float4 sm[TROWS * ROWF4];   // 8KB output tile

    int b    = blockIdx.y;
    int lane = threadIdx.x;                    // 0..7 (float4 half-row lane)
    int ty   = threadIdx.y;                    // 0..31
    int t    = blockIdx.x * TROWS + ty;

    float scale = __ldg(warp_scales + b);
    float start = (float)__ldg(window_starts + b);
    float nl    = floorf(205.0f * scale);
    float Lm1   = (2048.0f - 205.0f + nl) - 1.0f;
    float wend  = start + nl;
    float r204  = 204.0f / fmaxf(nl - 1.0f, 1.0f);

    // outer resample position (exact division to match reference rounding)
    float u = fminf((float)t * Lm1 / 2047.0f, Lm1);
    float j0 = floorf(u);
    float fu = u - j0;
    float j1 = fminf(j0 + 1.0f, 2252.0f);

    // 4 taps: indices + weights
    int   idx[4];
    float w[4];
    float jj[2] = {j0, j1};
#pragma unroll
    for (int q = 0; q < 2; q++) {
        float j = jj[q];
        float s = j;
        if (j >= start) s = fmaf(j - start, r204, start);
        if (j >= wend)  s = j - nl + 205.0f;
        s = fminf(fmaxf(s, 0.0f), 2047.0f);
        float p0 = floorf(s);
        float fr = s - p0;
        int i0 = (int)p0;
        idx[2 * q]     = i0;
        idx[2 * q + 1] = min(i0 + 1, TT - 1);
        float wu = q ? fu : (1.0f - fu);
        w[2 * q]     = wu * (1.0f - fr);
        w[2 * q + 1] = wu * fr;
    }

    const float4* xb = reinterpret_cast<const float4*>(x + (size_t)b * TT * CC);

    // front-batch all 8 gathers as full 256B row pairs, ascending row order
    float4 gA[4], gB[4];
#pragma unroll
    for (int k = 0; k < 4; k++) {
        const float4* row = xb + idx[k] * ROWF4;
        gA[k] = __ldg(row + lane);
        gB[k] = __ldg(row + lane + 8);
    }

    float4 rA, rB;
    rA.x = gA[0].x * w[0]; rA.y = gA[0].y * w[0]; rA.z = gA[0].z * w[0]; rA.w = gA[0].w * w[0];
    rB.x = gB[0].x * w[0]; rB.y = gB[0].y * w[0]; rB.z = gB[0].z * w[0]; rB.w = gB[0].w * w[0];
#pragma unroll
    for (int k = 1; k < 4; k++) {
        rA.x = fmaf(gA[k].x, w[k], rA.x); rA.y = fmaf(gA[k].y, w[k], rA.y);
        rA.z = fmaf(gA[k].z, w[k], rA.z); rA.w = fmaf(gA[k].w, w[k], rA.w);
        rB.x = fmaf(gB[k].x, w[k], rB.x); rB.y = fmaf(gB[k].y, w[k], rB.y);
        rB.z = fmaf(gB[k].z, w[k], rB.z); rB.w = fmaf(gB[k].w, w[k], rB.w);
    }

    // stage into the block's contiguous 8KB output tile
    sm[ty * ROWF4 + lane]     = rA;
    sm[ty * ROWF4 + lane + 8] = rB;
    __syncthreads();

    // one TMA bulk store of the whole tile (generic->async proxy fence first)
    if (threadIdx.x == 0 && threadIdx.y == 0) {
        asm volatile("fence.proxy.async.shared::cta;" ::: "memory");
        float* dst = out + (size_t)b * TT * CC + (size_t)blockIdx.x * TROWS * CC;
        uint32_t src = smem_u32(sm);
        asm volatile(
            "cp.async.bulk.global.shared::cta.bulk_group [%0], [%1], %2;"
            :: "l"(dst), "r"(src), "n"(TILE_BYTES) : "memory");
        asm volatile("cp.async.bulk.commit_group;" ::: "memory");
        // keep CTA (and its smem) alive until the bulk store has read smem
        asm volatile("cp.async.bulk.wait_group.read 0;" ::: "memory");
    }
}

extern "C" void kernel_launch(void* const* d_in, const int* in_sizes, int n_in,
                              void* d_out, int out_size) {
    const float* x      = (const float*)d_in[0];
    const float* scales = (const float*)d_in[1];
    const int*   starts = (const int*)d_in[2];
    float* out = (float*)d_out;

    dim3 block(8, 32);           // 256 threads
    dim3 grid(TT / TROWS, BB);   // (64, 256)
    window_warp_kernel<<<grid, block>>>(x, scales, starts, out);
}

// round 8
// speedup vs baseline: 1.0114x; 1.0114x over previous
#include <cuda_runtime.h>
#include <cstdint>

// WindowWarp R8: R7 gather path + PER-WARP TMA bulk stores.
// Each warp (8 float4-lanes x 4 t-rows) owns 4 contiguous output rows = 1KB
// of smem; after __syncwarp its leader issues its own cp.async.bulk. No
// block-wide barrier; early warps stream their writes while late warps are
// still gathering.
// B=256, T=2048, C=64, WARP_SIZE=205, L_MAX=2253.

#define BB 256
#define TT 2048
#define CC 64
#define ROWF4 (CC / 4)   // 16 float4 per row
#define TROWS 32         // t rows per block
#define WROWS 4          // t rows per warp
#define WARP_BYTES (WROWS * CC * 4)   // 1024

__device__ __forceinline__ uint32_t smem_u32(const void* p) {
    uint32_t a;
    asm("{ .reg .u64 t; cvta.to.shared.u64 t, %1; cvt.u32.u64 %0, t; }"
        : "=r"(a) : "l"(p));
    return a;
}

__global__ void __launch_bounds__(256, 8) window_warp_kernel(
    const float* __restrict__ x,
    const float* __restrict__ warp_scales,
    const int*   __restrict__ window_starts,
    float* __restrict__ out)
{
    __shared__ float4 sm[TROWS * ROWF4];   // 8KB output tile

    int b    = blockIdx.y;
    int lane = threadIdx.x;                    // 0..7 (float4 half-row lane)
    int ty   = threadIdx.y;                    // 0..31
    int t    = blockIdx.x * TROWS + ty;

    float scale = __ldg(warp_scales + b);
    float start = (float)__ldg(window_starts + b);
    float nl    = floorf(205.0f * scale);
    float Lm1   = (2048.0f - 205.0f + nl) - 1.0f;
    float wend  = start + nl;
    float r204  = 204.0f / fmaxf(nl - 1.0f, 1.0f);

    // outer resample position (exact division to match reference rounding)
    float u = fminf((float)t * Lm1 / 2047.0f, Lm1);
    float j0 = floorf(u);
    float fu = u - j0;
    float j1 = fminf(j0 + 1.0f, 2252.0f);

    // 4 taps: indices + weights
    int   idx[4];
    float w[4];
    float jj[2] = {j0, j1};
#pragma unroll
    for (int q = 0; q < 2; q++) {
        float j = jj[q];
        float s = j;
        if (j >= start) s = fmaf(j - start, r204, start);
        if (j >= wend)  s = j - nl + 205.0f;
        s = fminf(fmaxf(s, 0.0f), 2047.0f);
        float p0 = floorf(s);
        float fr = s - p0;
        int i0 = (int)p0;
        idx[2 * q]     = i0;
        idx[2 * q + 1] = min(i0 + 1, TT - 1);
        float wu = q ? fu : (1.0f - fu);
        w[2 * q]     = wu * (1.0f - fr);
        w[2 * q + 1] = wu * fr;
    }

    const float4* xb = reinterpret_cast<const float4*>(x + (size_t)b * TT * CC);

    // front-batch all 8 gathers as full 256B row pairs, ascending row order
    float4 gA[4], gB[4];
#pragma unroll
    for (int k = 0; k < 4; k++) {
        const float4* row = xb + idx[k] * ROWF4;
        gA[k] = __ldg(row + lane);
        gB[k] = __ldg(row + lane + 8);
    }

    float4 rA, rB;
    rA.x = gA[0].x * w[0]; rA.y = gA[0].y * w[0]; rA.z = gA[0].z * w[0]; rA.w = gA[0].w * w[0];
    rB.x = gB[0].x * w[0]; rB.y = gB[0].y * w[0]; rB.z = gB[0].z * w[0]; rB.w = gB[0].w * w[0];
#pragma unroll
    for (int k = 1; k < 4; k++) {
        rA.x = fmaf(gA[k].x, w[k], rA.x); rA.y = fmaf(gA[k].y, w[k], rA.y);
        rA.z = fmaf(gA[k].z, w[k], rA.z); rA.w = fmaf(gA[k].w, w[k], rA.w);
        rB.x = fmaf(gB[k].x, w[k], rB.x); rB.y = fmaf(gB[k].y, w[k], rB.y);
        rB.z = fmaf(gB[k].z, w[k], rB.z); rB.w = fmaf(gB[k].w, w[k], rB.w);
    }

    // stage this warp's 4 rows (1KB, contiguous in smem and in gmem)
    sm[ty * ROWF4 + lane]     = rA;
    sm[ty * ROWF4 + lane + 8] = rB;
    __syncwarp();

    // per-warp bulk store: warp leader ships its own 1KB chunk
    int tid = ty * 8 + lane;
    if ((tid & 31) == 0) {
        int warp_row0 = ty;   // leader has ty = 4*warp_id
        asm volatile("fence.proxy.async.shared::cta;" ::: "memory");
        float* dst = out + (size_t)b * TT * CC
                         + ((size_t)blockIdx.x * TROWS + warp_row0) * CC;
        uint32_t src = smem_u32(&sm[warp_row0 * ROWF4]);
        asm volatile(
            "cp.async.bulk.global.shared::cta.bulk_group [%0], [%1], %2;"
            :: "l"(dst), "r"(src), "n"(WARP_BYTES) : "memory");
        asm volatile("cp.async.bulk.commit_group;" ::: "memory");
        // keep smem alive until the bulk store has read it
        asm volatile("cp.async.bulk.wait_group.read 0;" ::: "memory");
    }
}

extern "C" void kernel_launch(void* const* d_in, const int* in_sizes, int n_in,
                              void* d_out, int out_size) {
    const float* x      = (const float*)d_in[0];
    const float* scales = (const float*)d_in[1];
    const int*   starts = (const int*)d_in[2];
    float* out = (float*)d_out;

    dim3 block(8, 32);           // 256 threads
    dim3 grid(TT / TROWS, BB);   // (64, 256)
    window_warp_kernel<<<grid, block>>>(x, scales, starts, out);
}